// round 16
// baseline (speedup 1.0000x reference)
#include <cuda_runtime.h>
#include <cuda_fp16.h>

#define HEADS 8
#define HEAD_DIM 32
#define BATCH 16
#define CDIM 256
#define NTOK 1024                 // 32*32
#define DIMQK (HEADS*HEAD_DIM)    // 256
#define RELW 3969                 // (2*32-1)^2
#define SCALE 0.17677669529663689f
#define LOG2E 1.4426950408889634f

typedef unsigned int u32;

// ---- helpers ---------------------------------------------------------------
__device__ __forceinline__ u32 pkh2(float a, float b) {
    __half2 h = __floats2half2_rn(a, b);
    return *(u32*)&h;
}
__device__ __forceinline__ uint2 cvt4h(float4 v) {
    return make_uint2(pkh2(v.x, v.y), pkh2(v.z, v.w));
}
__device__ __forceinline__ void mma16(float* c,
                                      u32 a0, u32 a1, u32 a2, u32 a3,
                                      u32 b0, u32 b1) {
    asm("mma.sync.aligned.m16n8k16.row.col.f32.f16.f16.f32 "
        "{%0,%1,%2,%3}, {%4,%5,%6,%7}, {%8,%9}, {%0,%1,%2,%3};"
        : "+f"(c[0]), "+f"(c[1]), "+f"(c[2]), "+f"(c[3])
        : "r"(a0), "r"(a1), "r"(a2), "r"(a3), "r"(b0), "r"(b1));
}
__device__ __forceinline__ u32 sptr(const void* p) {
    return (u32)__cvta_generic_to_shared(p);
}
__device__ __forceinline__ void ldsm_x4(u32& a, u32& b, u32& c, u32& d, u32 addr) {
    asm volatile("ldmatrix.sync.aligned.m8n8.x4.shared.b16 {%0,%1,%2,%3}, [%4];"
                 : "=r"(a), "=r"(b), "=r"(c), "=r"(d) : "r"(addr));
}
__device__ __forceinline__ void ldsm_x4_t(u32& a, u32& b, u32& c, u32& d, u32 addr) {
    asm volatile("ldmatrix.sync.aligned.m8n8.x4.trans.shared.b16 {%0,%1,%2,%3}, [%4];"
                 : "=r"(a), "=r"(b), "=r"(c), "=r"(d) : "r"(addr));
}
__device__ __forceinline__ void ldsm_x2_t(u32& a, u32& b, u32 addr) {
    asm volatile("ldmatrix.sync.aligned.m8n8.x2.trans.shared.b16 {%0,%1}, [%2];"
                 : "=r"(a), "=r"(b) : "r"(addr));
}
__device__ __forceinline__ u32 ex2h2(u32 x) {
    u32 r; asm("ex2.approx.f16x2 %0, %1;" : "=r"(r) : "r"(x)); return r;
}
__device__ __forceinline__ u32 hadd2u(u32 a, u32 b) {
    __half2 r = __hadd2(*(__half2*)&a, *(__half2*)&b);
    return *(u32*)&r;
}
__device__ __forceinline__ void cpa16(u32 saddr, const void* g) {
    asm volatile("cp.async.ca.shared.global [%0], [%1], 16;" :: "r"(saddr), "l"(g));
}
#define CP_COMMIT() asm volatile("cp.async.commit_group;")
#define CP_WAIT(n)  asm volatile("cp.async.wait_group %0;" :: "n"(n))

// Scratch (device globals: allocation-free contract)
__device__ __half g_xh[BATCH*NTOK*CDIM];            // x transposed [b][p][c] fp16
__device__ __half g_wh[4*DIMQK*CDIM];               // Wq|Wk|Wv|Wo fp16
__device__ __half g_q[BATCH*HEADS*NTOK*HEAD_DIM];
__device__ __half g_k[BATCH*HEADS*NTOK*HEAD_DIM];   // pre-scaled by SCALE*LOG2E
__device__ __half g_v[BATCH*HEADS*NTOK*HEAD_DIM];
__device__ __half g_ao[BATCH*NTOK*DIMQK];           // attention output [b][n][dim]
// bias table in mma A/C-fragment order:
// [h][qg(16-row group)][kt(64-key tile)][kp 0..3][lane] -> uint4{ba0,bb0,ba1,bb1}
__device__ uint4 g_biasf[HEADS*64*16*4*32];

// ---------------------------------------------------------------------------
// Prep A: transpose+convert x -> g_xh[b][p][c] fp16
// ---------------------------------------------------------------------------
__global__ __launch_bounds__(1024) void cvt_x_kernel(const float* __restrict__ x) {
    __shared__ __half T[32][33];
    const int tx = threadIdx.x, ty = threadIdx.y;
    const int p0 = blockIdx.x * 32, c0 = blockIdx.y * 32, bb = blockIdx.z;
    T[ty][tx] = __float2half(x[((size_t)bb * CDIM + c0 + ty) * NTOK + p0 + tx]);
    __syncthreads();
    g_xh[((size_t)bb * NTOK + p0 + ty) * CDIM + c0 + tx] = T[tx][ty];
}

// ---------------------------------------------------------------------------
// Prep B (fused): blocks [0,4096) build the fragment-permuted bias table;
// blocks [4096,4352) convert W matrices to fp16.
// ---------------------------------------------------------------------------
__global__ __launch_bounds__(256) void prep_kernel(const float* __restrict__ rel_bias,
                                                   const int*   __restrict__ rel_idx,
                                                   const float* __restrict__ Wq,
                                                   const float* __restrict__ Wk,
                                                   const float* __restrict__ Wv,
                                                   const float* __restrict__ Wo) {
    if (blockIdx.x < 4096) {
        const int e = blockIdx.x * 256 + threadIdx.x;   // uint4 entry id
        const int lane = e & 31;
        const int kp   = (e >> 5) & 3;
        const int kt   = (e >> 7) & 15;
        const int qg   = (e >> 11) & 63;
        const int h    = e >> 17;
        const int g = lane >> 2, t = lane & 3;

        const int q  = qg * 16 + g;
        const int k0 = kt * 64 + kp * 16 + 2 * t;
        const int k1 = k0 + 8;

        const int* ir  = rel_idx + (size_t)q * NTOK;
        const int* ir8 = rel_idx + (size_t)(q + 8) * NTOK;
        const float* bh = rel_bias + (size_t)h * RELW;

        uint4 o;
        o.x = pkh2(__ldg(&bh[ir[k0]])  * LOG2E, __ldg(&bh[ir[k0 + 1]])  * LOG2E);
        o.y = pkh2(__ldg(&bh[ir8[k0]]) * LOG2E, __ldg(&bh[ir8[k0 + 1]]) * LOG2E);
        o.z = pkh2(__ldg(&bh[ir[k1]])  * LOG2E, __ldg(&bh[ir[k1 + 1]])  * LOG2E);
        o.w = pkh2(__ldg(&bh[ir8[k1]]) * LOG2E, __ldg(&bh[ir8[k1 + 1]]) * LOG2E);
        g_biasf[e] = o;
    } else {
        const int id = (blockIdx.x - 4096) * 256 + threadIdx.x;
        const int base = id * 4;
        const int which = base >> 16, idx = base & 65535;
        const float* W = (which == 0) ? Wq : (which == 1) ? Wk : (which == 2) ? Wv : Wo;
        float4 v = *(const float4*)&W[idx];
        *(uint2*)&g_wh[base] = cvt4h(v);
    }
}

// ---------------------------------------------------------------------------
// Kernel 1: fused QKV via fp16 mma, 3-stage cp.async, B-pair ldsm_x4.
// ---------------------------------------------------------------------------
__global__ __launch_bounds__(256, 2) void qkv_kernel() {
    __shared__ __align__(16) __half Xs[3][128][24];
    __shared__ __align__(16) __half Ws[3][128][24];

    const int tid = threadIdx.x;
    const int lane = tid & 31, wid = tid >> 5;
    const int wm = (wid & 1) * 64;
    const int wn = (wid >> 1) * 32;

    const int arow = lane & 15, ahalf = (lane >> 4) * 8;
    const int bprow = (lane & 7) + (lane >> 4) * 8;
    const int bphalf = ((lane >> 3) & 1) * 8;

    const int p0 = blockIdx.x * 128;
    const int d0 = blockIdx.y * 128;
    const int which = blockIdx.z % 3;
    const int bb    = blockIdx.z / 3;

    __half* outp = (which == 0) ? g_q : (which == 1) ? g_k : g_v;
    const __half* xsrc = g_xh + ((size_t)bb * NTOK + p0) * CDIM;
    const __half* wsrc = g_wh + which * (DIMQK * CDIM) + (size_t)d0 * CDIM;

    const int lrow = tid >> 1, loff = (tid & 1) * 8;

    float acc[4][4][4] = {};

    #pragma unroll
    for (int s = 0; s < 2; s++) {
        cpa16(sptr(&Xs[s][lrow][loff]), xsrc + (size_t)lrow * CDIM + s * 16 + loff);
        cpa16(sptr(&Ws[s][lrow][loff]), wsrc + (size_t)lrow * CDIM + s * 16 + loff);
        CP_COMMIT();
    }

    for (int it = 0; it < CDIM / 16; it++) {
        const int buf = it % 3;
        if (it + 1 < CDIM / 16) { CP_WAIT(1); } else { CP_WAIT(0); }
        __syncthreads();

        if (it + 2 < CDIM / 16) {
            const int nb = (it + 2) % 3;
            const int c0 = (it + 2) * 16;
            cpa16(sptr(&Xs[nb][lrow][loff]), xsrc + (size_t)lrow * CDIM + c0 + loff);
            cpa16(sptr(&Ws[nb][lrow][loff]), wsrc + (size_t)lrow * CDIM + c0 + loff);
            CP_COMMIT();
        }

        const u32 xs_base = sptr(&Xs[buf][0][0]);
        const u32 ws_base = sptr(&Ws[buf][0][0]);
        u32 af[4][4];
        #pragma unroll
        for (int mt = 0; mt < 4; mt++) {
            const u32 addr = xs_base + ((wm + mt * 16 + arow) * 24 + ahalf) * 2;
            ldsm_x4(af[mt][0], af[mt][1], af[mt][2], af[mt][3], addr);
        }
        #pragma unroll
        for (int ntp = 0; ntp < 2; ntp++) {
            u32 b0, b1, b2, b3;
            const u32 addr = ws_base + ((wn + ntp * 16 + bprow) * 24 + bphalf) * 2;
            ldsm_x4(b0, b1, b2, b3, addr);
            #pragma unroll
            for (int mt = 0; mt < 4; mt++) {
                mma16(acc[mt][ntp * 2],     af[mt][0], af[mt][1], af[mt][2], af[mt][3], b0, b1);
                mma16(acc[mt][ntp * 2 + 1], af[mt][0], af[mt][1], af[mt][2], af[mt][3], b2, b3);
            }
        }
    }

    const int g = lane >> 2, t = lane & 3;
    const float sc = (which == 1) ? SCALE * LOG2E : 1.0f;
    #pragma unroll
    for (int mt = 0; mt < 4; mt++) {
        const int pr0 = p0 + wm + mt * 16 + g;
        #pragma unroll
        for (int nt = 0; nt < 4; nt++) {
            const int dim = d0 + wn + nt * 8 + 2 * t;
            const int h = dim >> 5, dd = dim & 31;
            __half* base0 = &outp[(((size_t)bb * HEADS + h) * NTOK + pr0) * HEAD_DIM + dd];
            __half* base1 = &outp[(((size_t)bb * HEADS + h) * NTOK + pr0 + 8) * HEAD_DIM + dd];
            *(u32*)base0 = pkh2(acc[mt][nt][0] * sc, acc[mt][nt][1] * sc);
            *(u32*)base1 = pkh2(acc[mt][nt][2] * sc, acc[mt][nt][3] * sc);
        }
    }
}

// ---------------------------------------------------------------------------
// Kernel 2: attention.  128-q blocks, 128 thr = 4 warps; warp owns 32 q rows
// (2 m-tiles).  64-key tiles processed as FOUR 16-key chunks, each doing
// S-mma -> exp -> PV-mma immediately: live P shrinks to 8 regs, enabling
// 5 CTAs/SM.  Fragment-order bias via coalesced LDG.128; ones-column
// normalizer; 2-stage cp.async K/V.
// ---------------------------------------------------------------------------
__global__ __launch_bounds__(128, 5) void attn_kernel() {
    __shared__ __align__(16) __half Ks[2][64][40];   // [key][d]
    __shared__ __align__(16) __half Vs[2][64][40];   // [key][d | ones col 32]
    __shared__ __align__(16) __half Qs[128][40];     // Q staging

    const int tid = threadIdx.x;
    const int lane = tid & 31, wid = tid >> 5;
    const int g = lane >> 2, t = lane & 3;
    const int m0 = wid * 32;           // warp's q offset (2 m-tiles)

    const int arow = lane & 15, ahalf = (lane >> 4) * 8;
    const int bprow = (lane & 7) + (lane >> 4) * 8;
    const int bphalf = ((lane >> 3) & 1) * 8;
    const int trow = lane & 7;
    const int tkhalf = ((lane >> 3) & 1) * 8;
    const int tdoff = (lane >> 4) * 8;

    const int q0 = blockIdx.x * 128;
    const int h  = blockIdx.y;
    const int bb = blockIdx.z;

    const size_t ho = ((size_t)bb * HEADS + h) * NTOK * HEAD_DIM;
    const __half* qb = g_q + ho;
    const __half* kb = g_k + ho;
    const __half* vb = g_v + ho;

    // ones columns (col 32) for both V stages
    {
        const int s = tid >> 6, key = tid & 63;
        u32* r = (u32*)&Vs[s][key][32];
        r[0] = 0x00003C00u;  r[1] = 0; r[2] = 0; r[3] = 0;
    }

    // Q staging: each thread one row
    {
        const __half* src = &qb[(size_t)(q0 + tid) * HEAD_DIM];
        *(uint4*)&Qs[tid][0]  = *(const uint4*)&src[0];
        *(uint4*)&Qs[tid][8]  = *(const uint4*)&src[8];
        *(uint4*)&Qs[tid][16] = *(const uint4*)&src[16];
        *(uint4*)&Qs[tid][24] = *(const uint4*)&src[24];
    }

    // cp.async prologue: K/V tile 0
    const int skey = tid >> 1, sdq = (tid & 1) * 16;
    cpa16(sptr(&Ks[0][skey][sdq]),     kb + (size_t)skey * HEAD_DIM + sdq);
    cpa16(sptr(&Ks[0][skey][sdq + 8]), kb + (size_t)skey * HEAD_DIM + sdq + 8);
    cpa16(sptr(&Vs[0][skey][sdq]),     vb + (size_t)skey * HEAD_DIM + sdq);
    cpa16(sptr(&Vs[0][skey][sdq + 8]), vb + (size_t)skey * HEAD_DIM + sdq + 8);
    CP_COMMIT();

    __syncthreads();   // Qs + ones visible

    u32 qa[2][2][4];   // [mt][kd]
    const u32 qs_base = sptr(&Qs[0][0]);
    #pragma unroll
    for (int mt = 0; mt < 2; mt++)
        #pragma unroll
        for (int kd = 0; kd < 2; kd++) {
            const u32 addr = qs_base + ((m0 + mt * 16 + arow) * 40 + kd * 16 + ahalf) * 2;
            ldsm_x4(qa[mt][kd][0], qa[mt][kd][1], qa[mt][kd][2], qa[mt][kd][3], addr);
        }

    float out[2][5][4] = {};   // [mt][nt 0..3 d, 4 ones][c]

    const int qg0 = blockIdx.x * 8 + wid * 2;     // 16-row q groups for mt 0/1
    const uint4* bf0p = g_biasf + (((size_t)h * 64 + qg0) * 16) * 4 * 32 + lane;
    const uint4* bf1p = g_biasf + (((size_t)h * 64 + qg0 + 1) * 16) * 4 * 32 + lane;

    for (int kt = 0; kt < NTOK / 64; kt++) {
        const int kbase = kt * 64;
        const int buf = kt & 1;

        CP_WAIT(0);
        __syncthreads();   // K/V(kt) visible; all warps done with buf^1

        if (kt + 1 < NTOK / 64) {
            const int nb = buf ^ 1;
            const __half* kn = kb + (size_t)(kbase + 64 + skey) * HEAD_DIM + sdq;
            const __half* vn = vb + (size_t)(kbase + 64 + skey) * HEAD_DIM + sdq;
            cpa16(sptr(&Ks[nb][skey][sdq]),     kn);
            cpa16(sptr(&Ks[nb][skey][sdq + 8]), kn + 8);
            cpa16(sptr(&Vs[nb][skey][sdq]),     vn);
            cpa16(sptr(&Vs[nb][skey][sdq + 8]), vn + 8);
            CP_COMMIT();
        }

        const u32 ks_base = sptr(&Ks[buf][0][0]);
        const u32 vs_base = sptr(&Vs[buf][0][0]);

        // process 64 keys as 4 chunks of 16: S -> exp -> PV per chunk
        #pragma unroll
        for (int kc = 0; kc < 4; kc++) {
            uint4 bfA = __ldg(bf0p + (kt * 4 + kc) * 32);
            uint4 bfB = __ldg(bf1p + (kt * 4 + kc) * 32);

            // S for 16 keys (2 n-tiles), both m-tiles
            float sA0[4] = {}, sA1[4] = {}, sB0[4] = {}, sB1[4] = {};
            #pragma unroll
            for (int kd = 0; kd < 2; kd++) {
                u32 b0, b1, b2, b3;
                const u32 addr = ks_base + ((kc * 16 + bprow) * 40 + kd * 16 + bphalf) * 2;
                ldsm_x4(b0, b1, b2, b3, addr);
                mma16(sA0, qa[0][kd][0], qa[0][kd][1], qa[0][kd][2], qa[0][kd][3], b0, b1);
                mma16(sA1, qa[0][kd][0], qa[0][kd][1], qa[0][kd][2], qa[0][kd][3], b2, b3);
                mma16(sB0, qa[1][kd][0], qa[1][kd][1], qa[1][kd][2], qa[1][kd][3], b0, b1);
                mma16(sB1, qa[1][kd][0], qa[1][kd][1], qa[1][kd][2], qa[1][kd][3], b2, b3);
            }

            // exp -> packed PV A-frags (live only within this chunk)
            const u32 aA0 = ex2h2(hadd2u(pkh2(sA0[0], sA0[1]), bfA.x));
            const u32 aA1 = ex2h2(hadd2u(pkh2(sA0[2], sA0[3]), bfA.y));
            const u32 aA2 = ex2h2(hadd2u(pkh2(sA1[0], sA1[1]), bfA.z));
            const u32 aA3 = ex2h2(hadd2u(pkh2(sA1[2], sA1[3]), bfA.w));
            const u32 aB0 = ex2h2(hadd2u(pkh2(sB0[0], sB0[1]), bfB.x));
            const u32 aB1 = ex2h2(hadd2u(pkh2(sB0[2], sB0[3]), bfB.y));
            const u32 aB2 = ex2h2(hadd2u(pkh2(sB1[0], sB1[1]), bfB.z));
            const u32 aB3 = ex2h2(hadd2u(pkh2(sB1[2], sB1[3]), bfB.w));

            // PV for this 16-key chunk; one V-frag set feeds both m-tiles
            u32 v0, v1, v2, v3, v4, v5, v6, v7, w0, w1;
            const u32 krow = kc * 16 + trow + tkhalf;
            ldsm_x4_t(v0, v1, v2, v3, vs_base + (krow * 40 + 0 + tdoff) * 2);
            ldsm_x4_t(v4, v5, v6, v7, vs_base + (krow * 40 + 16 + tdoff) * 2);
            ldsm_x2_t(w0, w1, vs_base + (krow * 40 + 32) * 2);

            mma16(out[0][0], aA0, aA1, aA2, aA3, v0, v1);
            mma16(out[0][1], aA0, aA1, aA2, aA3, v2, v3);
            mma16(out[0][2], aA0, aA1, aA2, aA3, v4, v5);
            mma16(out[0][3], aA0, aA1, aA2, aA3, v6, v7);
            mma16(out[0][4], aA0, aA1, aA2, aA3, w0, w1);
            mma16(out[1][0], aB0, aB1, aB2, aB3, v0, v1);
            mma16(out[1][1], aB0, aB1, aB2, aB3, v2, v3);
            mma16(out[1][2], aB0, aB1, aB2, aB3, v4, v5);
            mma16(out[1][3], aB0, aB1, aB2, aB3, v6, v7);
            mma16(out[1][4], aB0, aB1, aB2, aB3, w0, w1);
        }
    }

    // normalizers + write, per m-tile
    const int src = lane & 28;
    #pragma unroll
    for (int mt = 0; mt < 2; mt++) {
        const float l0 = __shfl_sync(0xFFFFFFFFu, out[mt][4][0], src);
        const float l1 = __shfl_sync(0xFFFFFFFFu, out[mt][4][2], src);
        const float inv0 = 1.0f / l0;
        const float inv1 = 1.0f / l1;
        const int qr0 = q0 + m0 + mt * 16 + g;
        const int qr1 = qr0 + 8;
        #pragma unroll
        for (int nt = 0; nt < 4; nt++) {
            const int dcol = h * HEAD_DIM + nt * 8 + 2 * t;
            *(u32*)&g_ao[((size_t)bb * NTOK + qr0) * DIMQK + dcol] =
                pkh2(out[mt][nt][0] * inv0, out[mt][nt][1] * inv0);
            *(u32*)&g_ao[((size_t)bb * NTOK + qr1) * DIMQK + dcol] =
                pkh2(out[mt][nt][2] * inv1, out[mt][nt][3] * inv1);
        }
    }
}

// ---------------------------------------------------------------------------
// Kernel 3: output projection via fp16 mma, 3-stage cp.async, B-pair ldsm_x4.
// ---------------------------------------------------------------------------
__global__ __launch_bounds__(256, 2) void proj_kernel(const float* __restrict__ bo,
                                                      float* __restrict__ y) {
    __shared__ __align__(16) __half As[3][128][24];
    __shared__ __align__(16) __half Bs[3][128][24];

    const int tid = threadIdx.x;
    const int lane = tid & 31, wid = tid >> 5;
    const int g = lane >> 2, t = lane & 3;
    const int wm = (wid & 1) * 64;
    const int wn = (wid >> 1) * 32;

    const int arow = lane & 15, ahalf = (lane >> 4) * 8;
    const int bprow = (lane & 7) + (lane >> 4) * 8;
    const int bphalf = ((lane >> 3) & 1) * 8;

    const int p0 = blockIdx.x * 128;
    const int c0 = blockIdx.y * 128;
    const int bb = blockIdx.z;

    const __half* asrc = g_wh + 3 * (DIMQK * CDIM) + (size_t)c0 * DIMQK;
    const __half* bsrc = g_ao + ((size_t)bb * NTOK + p0) * DIMQK;

    const int lrow = tid >> 1, loff = (tid & 1) * 8;

    float acc[4][4][4] = {};

    #pragma unroll
    for (int s = 0; s < 2; s++) {
        cpa16(sptr(&As[s][lrow][loff]), asrc + (size_t)lrow * DIMQK + s * 16 + loff);
        cpa16(sptr(&Bs[s][lrow][loff]), bsrc + (size_t)lrow * DIMQK + s * 16 + loff);
        CP_COMMIT();
    }

    for (int it = 0; it < DIMQK / 16; it++) {
        const int buf = it % 3;
        if (it + 1 < DIMQK / 16) { CP_WAIT(1); } else { CP_WAIT(0); }
        __syncthreads();

        if (it + 2 < DIMQK / 16) {
            const int nb = (it + 2) % 3;
            const int j0 = (it + 2) * 16;
            cpa16(sptr(&As[nb][lrow][loff]), asrc + (size_t)lrow * DIMQK + j0 + loff);
            cpa16(sptr(&Bs[nb][lrow][loff]), bsrc + (size_t)lrow * DIMQK + j0 + loff);
            CP_COMMIT();
        }

        const u32 as_base = sptr(&As[buf][0][0]);
        const u32 bs_base = sptr(&Bs[buf][0][0]);
        u32 af[4][4];
        #pragma unroll
        for (int mt = 0; mt < 4; mt++) {
            const u32 addr = as_base + ((wm + mt * 16 + arow) * 24 + ahalf) * 2;
            ldsm_x4(af[mt][0], af[mt][1], af[mt][2], af[mt][3], addr);
        }
        #pragma unroll
        for (int ntp = 0; ntp < 2; ntp++) {
            u32 b0, b1, b2, b3;
            const u32 addr = bs_base + ((wn + ntp * 16 + bprow) * 24 + bphalf) * 2;
            ldsm_x4(b0, b1, b2, b3, addr);
            #pragma unroll
            for (int mt = 0; mt < 4; mt++) {
                mma16(acc[mt][ntp * 2],     af[mt][0], af[mt][1], af[mt][2], af[mt][3], b0, b1);
                mma16(acc[mt][ntp * 2 + 1], af[mt][0], af[mt][1], af[mt][2], af[mt][3], b2, b3);
            }
        }
    }

    #pragma unroll
    for (int mt = 0; mt < 4; mt++) {
        const int cr0 = c0 + wm + mt * 16 + g;
        const float bias0 = __ldg(&bo[cr0]);
        const float bias1 = __ldg(&bo[cr0 + 8]);
        #pragma unroll
        for (int nt = 0; nt < 4; nt++) {
            const int pc = p0 + wn + nt * 8 + 2 * t;
            *(float2*)&y[((size_t)bb * CDIM + cr0) * NTOK + pc] =
                make_float2(acc[mt][nt][0] + bias0, acc[mt][nt][1] + bias0);
            *(float2*)&y[((size_t)bb * CDIM + cr0 + 8) * NTOK + pc] =
                make_float2(acc[mt][nt][2] + bias1, acc[mt][nt][3] + bias1);
        }
    }
}

// ---------------------------------------------------------------------------
extern "C" void kernel_launch(void* const* d_in, const int* in_sizes, int n_in,
                              void* d_out, int out_size) {
    const float* x        = (const float*)d_in[0];
    const float* Wq       = (const float*)d_in[1];
    const float* Wk       = (const float*)d_in[2];
    const float* Wv       = (const float*)d_in[3];
    const float* Wo       = (const float*)d_in[4];
    const float* bo       = (const float*)d_in[5];
    const float* rel_bias = (const float*)d_in[6];
    const int*   rel_idx  = (const int*)d_in[7];
    float* y = (float*)d_out;

    dim3 gx(NTOK / 32, CDIM / 32, BATCH);
    cvt_x_kernel<<<gx, dim3(32, 32)>>>(x);

    prep_kernel<<<4352, 256>>>(rel_bias, rel_idx, Wq, Wk, Wv, Wo);

    dim3 g1(NTOK / 128, DIMQK / 128, BATCH * 3);
    qkv_kernel<<<g1, 256>>>();

    dim3 g2(NTOK / 128, HEADS, BATCH);
    attn_kernel<<<g2, 128>>>();

    dim3 g3(NTOK / 128, CDIM / 128, BATCH);
    proj_kernel<<<g3, 256>>>(bo, y);
}

// round 17
// speedup vs baseline: 1.2508x; 1.2508x over previous
#include <cuda_runtime.h>
#include <cuda_fp16.h>

#define HEADS 8
#define HEAD_DIM 32
#define BATCH 16
#define CDIM 256
#define NTOK 1024                 // 32*32
#define DIMQK (HEADS*HEAD_DIM)    // 256
#define RELW 3969                 // (2*32-1)^2
#define SCALE 0.17677669529663689f
#define LOG2E 1.4426950408889634f

typedef unsigned int u32;

// ---- helpers ---------------------------------------------------------------
__device__ __forceinline__ u32 pkh2(float a, float b) {
    __half2 h = __floats2half2_rn(a, b);
    return *(u32*)&h;
}
__device__ __forceinline__ uint2 cvt4h(float4 v) {
    return make_uint2(pkh2(v.x, v.y), pkh2(v.z, v.w));
}
__device__ __forceinline__ void mma16(float* c,
                                      u32 a0, u32 a1, u32 a2, u32 a3,
                                      u32 b0, u32 b1) {
    asm("mma.sync.aligned.m16n8k16.row.col.f32.f16.f16.f32 "
        "{%0,%1,%2,%3}, {%4,%5,%6,%7}, {%8,%9}, {%0,%1,%2,%3};"
        : "+f"(c[0]), "+f"(c[1]), "+f"(c[2]), "+f"(c[3])
        : "r"(a0), "r"(a1), "r"(a2), "r"(a3), "r"(b0), "r"(b1));
}
__device__ __forceinline__ u32 sptr(const void* p) {
    return (u32)__cvta_generic_to_shared(p);
}
__device__ __forceinline__ void ldsm_x4(u32& a, u32& b, u32& c, u32& d, u32 addr) {
    asm volatile("ldmatrix.sync.aligned.m8n8.x4.shared.b16 {%0,%1,%2,%3}, [%4];"
                 : "=r"(a), "=r"(b), "=r"(c), "=r"(d) : "r"(addr));
}
__device__ __forceinline__ void ldsm_x4_t(u32& a, u32& b, u32& c, u32& d, u32 addr) {
    asm volatile("ldmatrix.sync.aligned.m8n8.x4.trans.shared.b16 {%0,%1,%2,%3}, [%4];"
                 : "=r"(a), "=r"(b), "=r"(c), "=r"(d) : "r"(addr));
}
__device__ __forceinline__ void ldsm_x2_t(u32& a, u32& b, u32 addr) {
    asm volatile("ldmatrix.sync.aligned.m8n8.x2.trans.shared.b16 {%0,%1}, [%2];"
                 : "=r"(a), "=r"(b) : "r"(addr));
}
__device__ __forceinline__ u32 ex2h2(u32 x) {
    u32 r; asm("ex2.approx.f16x2 %0, %1;" : "=r"(r) : "r"(x)); return r;
}
__device__ __forceinline__ u32 hadd2u(u32 a, u32 b) {
    __half2 r = __hadd2(*(__half2*)&a, *(__half2*)&b);
    return *(u32*)&r;
}
__device__ __forceinline__ void cpa16(u32 saddr, const void* g) {
    asm volatile("cp.async.ca.shared.global [%0], [%1], 16;" :: "r"(saddr), "l"(g));
}
#define CP_COMMIT() asm volatile("cp.async.commit_group;")
#define CP_WAIT(n)  asm volatile("cp.async.wait_group %0;" :: "n"(n))

// Scratch (device globals: allocation-free contract)
__device__ __half g_xh[BATCH*NTOK*CDIM];            // x transposed [b][p][c] fp16
__device__ __half g_wh[4*DIMQK*CDIM];               // Wq|Wk|Wv|Wo fp16
__device__ __half g_q[BATCH*HEADS*NTOK*HEAD_DIM];
__device__ __half g_k[BATCH*HEADS*NTOK*HEAD_DIM];   // pre-scaled by SCALE*LOG2E
__device__ __half g_v[BATCH*HEADS*NTOK*HEAD_DIM];
__device__ __half g_ao[BATCH*NTOK*DIMQK];           // attention output [b][n][dim]
// bias table in mma A/C-fragment order:
// [h][qg(16-row group)][kt(64-key tile)][kp 0..3][lane] -> uint4{ba0,bb0,ba1,bb1}
__device__ uint4 g_biasf[HEADS*64*16*4*32];

// ---------------------------------------------------------------------------
// Fused prep kernel, block-range dispatch (all independent work, one wave):
//   [0, 4096)       : fragment-permuted bias table
//   [4096, 4352)    : W matrices -> fp16
//   [4352, 8448)    : x transpose+convert -> g_xh (32x32 tiles, 256 thr)
// ---------------------------------------------------------------------------
__global__ __launch_bounds__(256) void prep_kernel(const float* __restrict__ rel_bias,
                                                   const int*   __restrict__ rel_idx,
                                                   const float* __restrict__ Wq,
                                                   const float* __restrict__ Wk,
                                                   const float* __restrict__ Wv,
                                                   const float* __restrict__ Wo,
                                                   const float* __restrict__ x) {
    if (blockIdx.x < 4096) {
        const int e = blockIdx.x * 256 + threadIdx.x;   // uint4 entry id
        const int lane = e & 31;
        const int kp   = (e >> 5) & 3;
        const int kt   = (e >> 7) & 15;
        const int qg   = (e >> 11) & 63;
        const int h    = e >> 17;
        const int g = lane >> 2, t = lane & 3;

        const int q  = qg * 16 + g;
        const int k0 = kt * 64 + kp * 16 + 2 * t;
        const int k1 = k0 + 8;

        const int* ir  = rel_idx + (size_t)q * NTOK;
        const int* ir8 = rel_idx + (size_t)(q + 8) * NTOK;
        const float* bh = rel_bias + (size_t)h * RELW;

        uint4 o;
        o.x = pkh2(__ldg(&bh[ir[k0]])  * LOG2E, __ldg(&bh[ir[k0 + 1]])  * LOG2E);
        o.y = pkh2(__ldg(&bh[ir8[k0]]) * LOG2E, __ldg(&bh[ir8[k0 + 1]]) * LOG2E);
        o.z = pkh2(__ldg(&bh[ir[k1]])  * LOG2E, __ldg(&bh[ir[k1 + 1]])  * LOG2E);
        o.w = pkh2(__ldg(&bh[ir8[k1]]) * LOG2E, __ldg(&bh[ir8[k1 + 1]]) * LOG2E);
        g_biasf[e] = o;
    } else if (blockIdx.x < 4352) {
        const int id = (blockIdx.x - 4096) * 256 + threadIdx.x;
        const int base = id * 4;
        const int which = base >> 16, idx = base & 65535;
        const float* W = (which == 0) ? Wq : (which == 1) ? Wk : (which == 2) ? Wv : Wo;
        float4 v = *(const float4*)&W[idx];
        *(uint2*)&g_wh[base] = cvt4h(v);
    } else {
        // x transpose: tile id -> (p0, c0, bb); 256 thr, 4 elems each
        __shared__ __half T[32][33];
        const int tile = blockIdx.x - 4352;            // 0..4095
        const int pt = tile & 31;                      // 32 p-tiles
        const int ct = (tile >> 5) & 7;                // 8 c-tiles
        const int bb = tile >> 8;                      // 16 batches
        const int p0 = pt * 32, c0 = ct * 32;
        const int tx = threadIdx.x & 31, ty = threadIdx.x >> 5;   // ty 0..7
        #pragma unroll
        for (int i = 0; i < 4; i++) {
            const int row = ty + 8 * i;                // c within tile
            T[row][tx] = __float2half(x[((size_t)bb * CDIM + c0 + row) * NTOK + p0 + tx]);
        }
        __syncthreads();
        #pragma unroll
        for (int i = 0; i < 4; i++) {
            const int prow = ty + 8 * i;               // p within tile
            g_xh[((size_t)bb * NTOK + p0 + prow) * CDIM + c0 + tx] = T[tx][prow];
        }
    }
}

// ---------------------------------------------------------------------------
// Kernel 1: fused QKV via fp16 mma, 3-stage cp.async, B-pair ldsm_x4.
// ---------------------------------------------------------------------------
__global__ __launch_bounds__(256, 2) void qkv_kernel() {
    __shared__ __align__(16) __half Xs[3][128][24];
    __shared__ __align__(16) __half Ws[3][128][24];

    const int tid = threadIdx.x;
    const int lane = tid & 31, wid = tid >> 5;
    const int wm = (wid & 1) * 64;
    const int wn = (wid >> 1) * 32;

    const int arow = lane & 15, ahalf = (lane >> 4) * 8;
    const int bprow = (lane & 7) + (lane >> 4) * 8;
    const int bphalf = ((lane >> 3) & 1) * 8;

    const int p0 = blockIdx.x * 128;
    const int d0 = blockIdx.y * 128;
    const int which = blockIdx.z % 3;
    const int bb    = blockIdx.z / 3;

    __half* outp = (which == 0) ? g_q : (which == 1) ? g_k : g_v;
    const __half* xsrc = g_xh + ((size_t)bb * NTOK + p0) * CDIM;
    const __half* wsrc = g_wh + which * (DIMQK * CDIM) + (size_t)d0 * CDIM;

    const int lrow = tid >> 1, loff = (tid & 1) * 8;

    float acc[4][4][4] = {};

    #pragma unroll
    for (int s = 0; s < 2; s++) {
        cpa16(sptr(&Xs[s][lrow][loff]), xsrc + (size_t)lrow * CDIM + s * 16 + loff);
        cpa16(sptr(&Ws[s][lrow][loff]), wsrc + (size_t)lrow * CDIM + s * 16 + loff);
        CP_COMMIT();
    }

    for (int it = 0; it < CDIM / 16; it++) {
        const int buf = it % 3;
        if (it + 1 < CDIM / 16) { CP_WAIT(1); } else { CP_WAIT(0); }
        __syncthreads();

        if (it + 2 < CDIM / 16) {
            const int nb = (it + 2) % 3;
            const int c0 = (it + 2) * 16;
            cpa16(sptr(&Xs[nb][lrow][loff]), xsrc + (size_t)lrow * CDIM + c0 + loff);
            cpa16(sptr(&Ws[nb][lrow][loff]), wsrc + (size_t)lrow * CDIM + c0 + loff);
            CP_COMMIT();
        }

        const u32 xs_base = sptr(&Xs[buf][0][0]);
        const u32 ws_base = sptr(&Ws[buf][0][0]);
        u32 af[4][4];
        #pragma unroll
        for (int mt = 0; mt < 4; mt++) {
            const u32 addr = xs_base + ((wm + mt * 16 + arow) * 24 + ahalf) * 2;
            ldsm_x4(af[mt][0], af[mt][1], af[mt][2], af[mt][3], addr);
        }
        #pragma unroll
        for (int ntp = 0; ntp < 2; ntp++) {
            u32 b0, b1, b2, b3;
            const u32 addr = ws_base + ((wn + ntp * 16 + bprow) * 24 + bphalf) * 2;
            ldsm_x4(b0, b1, b2, b3, addr);
            #pragma unroll
            for (int mt = 0; mt < 4; mt++) {
                mma16(acc[mt][ntp * 2],     af[mt][0], af[mt][1], af[mt][2], af[mt][3], b0, b1);
                mma16(acc[mt][ntp * 2 + 1], af[mt][0], af[mt][1], af[mt][2], af[mt][3], b2, b3);
            }
        }
    }

    const int g = lane >> 2, t = lane & 3;
    const float sc = (which == 1) ? SCALE * LOG2E : 1.0f;
    #pragma unroll
    for (int mt = 0; mt < 4; mt++) {
        const int pr0 = p0 + wm + mt * 16 + g;
        #pragma unroll
        for (int nt = 0; nt < 4; nt++) {
            const int dim = d0 + wn + nt * 8 + 2 * t;
            const int h = dim >> 5, dd = dim & 31;
            __half* base0 = &outp[(((size_t)bb * HEADS + h) * NTOK + pr0) * HEAD_DIM + dd];
            __half* base1 = &outp[(((size_t)bb * HEADS + h) * NTOK + pr0 + 8) * HEAD_DIM + dd];
            *(u32*)base0 = pkh2(acc[mt][nt][0] * sc, acc[mt][nt][1] * sc);
            *(u32*)base1 = pkh2(acc[mt][nt][2] * sc, acc[mt][nt][3] * sc);
        }
    }
}

// ---------------------------------------------------------------------------
// Kernel 2: attention (R15 structure).  128-q blocks, 128 thr = 4 warps;
// warp owns 32 q rows (2 m-tiles) so every K/V fragment feeds 2x mma work.
// Batched S-phase (4 independent ntp), then exp, then batched PV — max ILP.
// Fragment-order bias via coalesced LDG.128; register-resident P;
// ones-column normalizer; 2-stage cp.async K/V.
// ---------------------------------------------------------------------------
__global__ __launch_bounds__(128, 4) void attn_kernel() {
    __shared__ __align__(16) __half Ks[2][64][40];   // [key][d]
    __shared__ __align__(16) __half Vs[2][64][40];   // [key][d | ones col 32]
    __shared__ __align__(16) __half Qs[128][40];     // Q staging

    const int tid = threadIdx.x;
    const int lane = tid & 31, wid = tid >> 5;
    const int g = lane >> 2, t = lane & 3;
    const int m0 = wid * 32;           // warp's q offset (2 m-tiles)

    const int arow = lane & 15, ahalf = (lane >> 4) * 8;
    const int bprow = (lane & 7) + (lane >> 4) * 8;
    const int bphalf = ((lane >> 3) & 1) * 8;
    const int trow = lane & 7;
    const int tkhalf = ((lane >> 3) & 1) * 8;
    const int tdoff = (lane >> 4) * 8;

    const int q0 = blockIdx.x * 128;
    const int h  = blockIdx.y;
    const int bb = blockIdx.z;

    const size_t ho = ((size_t)bb * HEADS + h) * NTOK * HEAD_DIM;
    const __half* qb = g_q + ho;
    const __half* kb = g_k + ho;
    const __half* vb = g_v + ho;

    // ones columns (col 32) for both V stages
    {
        const int s = tid >> 6, key = tid & 63;
        u32* r = (u32*)&Vs[s][key][32];
        r[0] = 0x00003C00u;  r[1] = 0; r[2] = 0; r[3] = 0;
    }

    // Q staging: each thread one row
    {
        const __half* src = &qb[(size_t)(q0 + tid) * HEAD_DIM];
        *(uint4*)&Qs[tid][0]  = *(const uint4*)&src[0];
        *(uint4*)&Qs[tid][8]  = *(const uint4*)&src[8];
        *(uint4*)&Qs[tid][16] = *(const uint4*)&src[16];
        *(uint4*)&Qs[tid][24] = *(const uint4*)&src[24];
    }

    // cp.async prologue: K/V tile 0
    const int skey = tid >> 1, sdq = (tid & 1) * 16;
    cpa16(sptr(&Ks[0][skey][sdq]),     kb + (size_t)skey * HEAD_DIM + sdq);
    cpa16(sptr(&Ks[0][skey][sdq + 8]), kb + (size_t)skey * HEAD_DIM + sdq + 8);
    cpa16(sptr(&Vs[0][skey][sdq]),     vb + (size_t)skey * HEAD_DIM + sdq);
    cpa16(sptr(&Vs[0][skey][sdq + 8]), vb + (size_t)skey * HEAD_DIM + sdq + 8);
    CP_COMMIT();

    __syncthreads();   // Qs + ones visible

    u32 qa[2][2][4];   // [mt][ks]
    const u32 qs_base = sptr(&Qs[0][0]);
    #pragma unroll
    for (int mt = 0; mt < 2; mt++)
        #pragma unroll
        for (int ks = 0; ks < 2; ks++) {
            const u32 addr = qs_base + ((m0 + mt * 16 + arow) * 40 + ks * 16 + ahalf) * 2;
            ldsm_x4(qa[mt][ks][0], qa[mt][ks][1], qa[mt][ks][2], qa[mt][ks][3], addr);
        }

    float out[2][5][4] = {};   // [mt][nt 0..3 d, 4 ones][c]

    const int qg0 = blockIdx.x * 8 + wid * 2;     // 16-row q groups for mt 0/1
    const uint4* bf0p = g_biasf + (((size_t)h * 64 + qg0) * 16) * 4 * 32 + lane;
    const uint4* bf1p = g_biasf + (((size_t)h * 64 + qg0 + 1) * 16) * 4 * 32 + lane;

    for (int kt = 0; kt < NTOK / 64; kt++) {
        const int kbase = kt * 64;
        const int buf = kt & 1;

        CP_WAIT(0);
        __syncthreads();   // K/V(kt) visible; all warps done with buf^1

        if (kt + 1 < NTOK / 64) {
            const int nb = buf ^ 1;
            const __half* kn = kb + (size_t)(kbase + 64 + skey) * HEAD_DIM + sdq;
            const __half* vn = vb + (size_t)(kbase + 64 + skey) * HEAD_DIM + sdq;
            cpa16(sptr(&Ks[nb][skey][sdq]),     kn);
            cpa16(sptr(&Ks[nb][skey][sdq + 8]), kn + 8);
            cpa16(sptr(&Vs[nb][skey][sdq]),     vn);
            cpa16(sptr(&Vs[nb][skey][sdq + 8]), vn + 8);
            CP_COMMIT();
        }

        const u32 ks_base = sptr(&Ks[buf][0][0]);
        const u32 vs_base = sptr(&Vs[buf][0][0]);

        // S + exp per ntp: one K-frag pair feeds both m-tiles
        u32 p[2][8][2];   // [mt][nt][row-half]: packed exp'd scores (PV A-frags)
        #pragma unroll
        for (int ntp = 0; ntp < 4; ntp++) {
            uint4 bfA = __ldg(bf0p + (kt * 4 + ntp) * 32);
            uint4 bfB = __ldg(bf1p + (kt * 4 + ntp) * 32);
            float sA0[4] = {}, sA1[4] = {}, sB0[4] = {}, sB1[4] = {};
            #pragma unroll
            for (int ks = 0; ks < 2; ks++) {
                u32 b0, b1, b2, b3;
                const u32 addr = ks_base + ((ntp * 16 + bprow) * 40 + ks * 16 + bphalf) * 2;
                ldsm_x4(b0, b1, b2, b3, addr);
                mma16(sA0, qa[0][ks][0], qa[0][ks][1], qa[0][ks][2], qa[0][ks][3], b0, b1);
                mma16(sA1, qa[0][ks][0], qa[0][ks][1], qa[0][ks][2], qa[0][ks][3], b2, b3);
                mma16(sB0, qa[1][ks][0], qa[1][ks][1], qa[1][ks][2], qa[1][ks][3], b0, b1);
                mma16(sB1, qa[1][ks][0], qa[1][ks][1], qa[1][ks][2], qa[1][ks][3], b2, b3);
            }
            const int nt0 = ntp * 2, nt1 = ntp * 2 + 1;
            p[0][nt0][0] = ex2h2(hadd2u(pkh2(sA0[0], sA0[1]), bfA.x));
            p[0][nt0][1] = ex2h2(hadd2u(pkh2(sA0[2], sA0[3]), bfA.y));
            p[0][nt1][0] = ex2h2(hadd2u(pkh2(sA1[0], sA1[1]), bfA.z));
            p[0][nt1][1] = ex2h2(hadd2u(pkh2(sA1[2], sA1[3]), bfA.w));
            p[1][nt0][0] = ex2h2(hadd2u(pkh2(sB0[0], sB0[1]), bfB.x));
            p[1][nt0][1] = ex2h2(hadd2u(pkh2(sB0[2], sB0[3]), bfB.y));
            p[1][nt1][0] = ex2h2(hadd2u(pkh2(sB1[0], sB1[1]), bfB.z));
            p[1][nt1][1] = ex2h2(hadd2u(pkh2(sB1[2], sB1[3]), bfB.w));
        }

        // PV: one V-frag set feeds both m-tiles
        #pragma unroll
        for (int ks = 0; ks < 4; ks++) {
            u32 v0, v1, v2, v3, v4, v5, v6, v7, w0, w1;
            const u32 krow = ks * 16 + trow + tkhalf;
            ldsm_x4_t(v0, v1, v2, v3, vs_base + (krow * 40 + 0 + tdoff) * 2);
            ldsm_x4_t(v4, v5, v6, v7, vs_base + (krow * 40 + 16 + tdoff) * 2);
            ldsm_x2_t(w0, w1, vs_base + (krow * 40 + 32) * 2);
            #pragma unroll
            for (int mt = 0; mt < 2; mt++) {
                const u32 a0 = p[mt][2 * ks][0],     a1 = p[mt][2 * ks][1];
                const u32 a2 = p[mt][2 * ks + 1][0], a3 = p[mt][2 * ks + 1][1];
                mma16(out[mt][0], a0, a1, a2, a3, v0, v1);
                mma16(out[mt][1], a0, a1, a2, a3, v2, v3);
                mma16(out[mt][2], a0, a1, a2, a3, v4, v5);
                mma16(out[mt][3], a0, a1, a2, a3, v6, v7);
                mma16(out[mt][4], a0, a1, a2, a3, w0, w1);
            }
        }
    }

    // normalizers + write, per m-tile
    const int src = lane & 28;
    #pragma unroll
    for (int mt = 0; mt < 2; mt++) {
        const float l0 = __shfl_sync(0xFFFFFFFFu, out[mt][4][0], src);
        const float l1 = __shfl_sync(0xFFFFFFFFu, out[mt][4][2], src);
        const float inv0 = 1.0f / l0;
        const float inv1 = 1.0f / l1;
        const int qr0 = q0 + m0 + mt * 16 + g;
        const int qr1 = qr0 + 8;
        #pragma unroll
        for (int nt = 0; nt < 4; nt++) {
            const int dcol = h * HEAD_DIM + nt * 8 + 2 * t;
            *(u32*)&g_ao[((size_t)bb * NTOK + qr0) * DIMQK + dcol] =
                pkh2(out[mt][nt][0] * inv0, out[mt][nt][1] * inv0);
            *(u32*)&g_ao[((size_t)bb * NTOK + qr1) * DIMQK + dcol] =
                pkh2(out[mt][nt][2] * inv1, out[mt][nt][3] * inv1);
        }
    }
}

// ---------------------------------------------------------------------------
// Kernel 3: output projection via fp16 mma, 3-stage cp.async, B-pair ldsm_x4.
// ---------------------------------------------------------------------------
__global__ __launch_bounds__(256, 2) void proj_kernel(const float* __restrict__ bo,
                                                      float* __restrict__ y) {
    __shared__ __align__(16) __half As[3][128][24];
    __shared__ __align__(16) __half Bs[3][128][24];

    const int tid = threadIdx.x;
    const int lane = tid & 31, wid = tid >> 5;
    const int g = lane >> 2, t = lane & 3;
    const int wm = (wid & 1) * 64;
    const int wn = (wid >> 1) * 32;

    const int arow = lane & 15, ahalf = (lane >> 4) * 8;
    const int bprow = (lane & 7) + (lane >> 4) * 8;
    const int bphalf = ((lane >> 3) & 1) * 8;

    const int p0 = blockIdx.x * 128;
    const int c0 = blockIdx.y * 128;
    const int bb = blockIdx.z;

    const __half* asrc = g_wh + 3 * (DIMQK * CDIM) + (size_t)c0 * DIMQK;
    const __half* bsrc = g_ao + ((size_t)bb * NTOK + p0) * DIMQK;

    const int lrow = tid >> 1, loff = (tid & 1) * 8;

    float acc[4][4][4] = {};

    #pragma unroll
    for (int s = 0; s < 2; s++) {
        cpa16(sptr(&As[s][lrow][loff]), asrc + (size_t)lrow * DIMQK + s * 16 + loff);
        cpa16(sptr(&Bs[s][lrow][loff]), bsrc + (size_t)lrow * DIMQK + s * 16 + loff);
        CP_COMMIT();
    }

    for (int it = 0; it < DIMQK / 16; it++) {
        const int buf = it % 3;
        if (it + 1 < DIMQK / 16) { CP_WAIT(1); } else { CP_WAIT(0); }
        __syncthreads();

        if (it + 2 < DIMQK / 16) {
            const int nb = (it + 2) % 3;
            const int j0 = (it + 2) * 16;
            cpa16(sptr(&As[nb][lrow][loff]), asrc + (size_t)lrow * DIMQK + j0 + loff);
            cpa16(sptr(&Bs[nb][lrow][loff]), bsrc + (size_t)lrow * DIMQK + j0 + loff);
            CP_COMMIT();
        }

        const u32 as_base = sptr(&As[buf][0][0]);
        const u32 bs_base = sptr(&Bs[buf][0][0]);
        u32 af[4][4];
        #pragma unroll
        for (int mt = 0; mt < 4; mt++) {
            const u32 addr = as_base + ((wm + mt * 16 + arow) * 24 + ahalf) * 2;
            ldsm_x4(af[mt][0], af[mt][1], af[mt][2], af[mt][3], addr);
        }
        #pragma unroll
        for (int ntp = 0; ntp < 2; ntp++) {
            u32 b0, b1, b2, b3;
            const u32 addr = bs_base + ((wn + ntp * 16 + bprow) * 24 + bphalf) * 2;
            ldsm_x4(b0, b1, b2, b3, addr);
            #pragma unroll
            for (int mt = 0; mt < 4; mt++) {
                mma16(acc[mt][ntp * 2],     af[mt][0], af[mt][1], af[mt][2], af[mt][3], b0, b1);
                mma16(acc[mt][ntp * 2 + 1], af[mt][0], af[mt][1], af[mt][2], af[mt][3], b2, b3);
            }
        }
    }

    #pragma unroll
    for (int mt = 0; mt < 4; mt++) {
        const int cr0 = c0 + wm + mt * 16 + g;
        const float bias0 = __ldg(&bo[cr0]);
        const float bias1 = __ldg(&bo[cr0 + 8]);
        #pragma unroll
        for (int nt = 0; nt < 4; nt++) {
            const int pc = p0 + wn + nt * 8 + 2 * t;
            *(float2*)&y[((size_t)bb * CDIM + cr0) * NTOK + pc] =
                make_float2(acc[mt][nt][0] + bias0, acc[mt][nt][1] + bias0);
            *(float2*)&y[((size_t)bb * CDIM + cr0 + 8) * NTOK + pc] =
                make_float2(acc[mt][nt][2] + bias1, acc[mt][nt][3] + bias1);
        }
    }
}

// ---------------------------------------------------------------------------
extern "C" void kernel_launch(void* const* d_in, const int* in_sizes, int n_in,
                              void* d_out, int out_size) {
    const float* x        = (const float*)d_in[0];
    const float* Wq       = (const float*)d_in[1];
    const float* Wk       = (const float*)d_in[2];
    const float* Wv       = (const float*)d_in[3];
    const float* Wo       = (const float*)d_in[4];
    const float* bo       = (const float*)d_in[5];
    const float* rel_bias = (const float*)d_in[6];
    const int*   rel_idx  = (const int*)d_in[7];
    float* y = (float*)d_out;

    // fused prep: bias table + W cvt + x transpose, one wave
    prep_kernel<<<8448, 256>>>(rel_bias, rel_idx, Wq, Wk, Wv, Wo, x);

    dim3 g1(NTOK / 128, DIMQK / 128, BATCH * 3);
    qkv_kernel<<<g1, 256>>>();

    dim3 g2(NTOK / 128, HEADS, BATCH);
    attn_kernel<<<g2, 128>>>();

    dim3 g3(NTOK / 128, CDIM / 128, BATCH);
    proj_kernel<<<g3, 256>>>(bo, y);
}